// round 8
// baseline (speedup 1.0000x reference)
#include <cuda_runtime.h>

// Blocks_86096914416144 — SNN block scan, R8: 2 lanes per thread, all x-loads
// LDG.64 and spike stores STG.64 (halves memory warp-instruction count; same
// 3MB in flight). Evidence R5-R7: runtime insensitive to ALU instr count,
// DRAM stuck ~48-54% -> memory-side ceiling; attack request count/width.
// Per-lane math = R7 first-spike-index body (rel_err 0.0 proven).

#define T_LEN   1024
#define TB      8
#define NBLK    (T_LEN / TB)      // 128
#define BATCH   32
#define NOUT    1024
#define BN      (BATCH * NOUT)    // 32768
#define NTHREAD (BN / 2)          // 16384, 2 lanes per thread
#define CTA     64

__global__ __launch_bounds__(CTA)
void blocks_snn_kernel(const float* __restrict__ x,
                       const float* __restrict__ beta_raw,
                       const float* __restrict__ p_raw,
                       const float* __restrict__ b_raw,
                       float* __restrict__ out)
{
    const int tid  = blockIdx.x * CTA + threadIdx.x;   // 0..16383
    const int base = 2 * tid;                           // first lane id
    const int n0   = base & (NOUT - 1);                 // even; lanes n0, n0+1

    // per-lane params (vector loads: n0 is even -> 8B aligned)
    const float2 brv = *(const float2*)(beta_raw + n0);
    const float2 prv = *(const float2*)(p_raw    + n0);
    const float2 bbv = *(const float2*)(b_raw    + n0);

    float beta[2], p[2], bb[2], inv_p[2];
    beta[0] = fminf(fmaxf(brv.x, 0.001f), 0.999f);
    beta[1] = fminf(fmaxf(brv.y, 0.001f), 0.999f);
    p[0]    = fminf(fmaxf(fabsf(prv.x), 0.0f), 0.999f);
    p[1]    = fminf(fmaxf(fabsf(prv.y), 0.0f), 0.999f);
    bb[0]   = fminf(fmaxf(fabsf(bbv.x), 0.001f), 1.0f);
    bb[1]   = fminf(fmaxf(fabsf(bbv.y), 0.001f), 1.0f);
    inv_p[0] = 1.0f / p[0];
    inv_p[1] = 1.0f / p[1];

    float bpow[2][TB], ppow[2][TB + 1];
    #pragma unroll
    for (int l = 0; l < 2; l++) {
        bpow[l][0] = 1.0f;
        #pragma unroll
        for (int k = 1; k < TB; k++) bpow[l][k] = powf(beta[l], (float)k);
        ppow[l][0] = 1.0f;
        #pragma unroll
        for (int k = 1; k <= TB; k++) ppow[l][k] = powf(p[l], (float)k);
    }

    // carry per lane: first-spike index (TB = none), a, vmem
    int   t0p[2]  = {TB, TB};
    float a[2]    = {0.0f, 0.0f};
    float vmem[2] = {0.0f, 0.0f};

    const float2* xp = (const float2*)(x + base);
    float2*       op = (float2*)(out + base);
    const int     BN2 = BN / 2;    // float2 stride per t

    // 4-slot register ring of float2, prefetch 3 blocks ahead
    float2 buf[4][TB];
    #pragma unroll
    for (int pb = 0; pb < 3; pb++) {
        const float2* xb = xp + (size_t)pb * TB * BN2;
        #pragma unroll
        for (int t = 0; t < TB; t++) buf[pb][t] = xb[t * BN2];
    }

    #pragma unroll 1
    for (int g = 0; g < NBLK / 4; g++) {
        #pragma unroll
        for (int u = 0; u < 4; u++) {
            const int blk = 4 * g + u;

            if (blk + 3 < NBLK) {
                const float2* xb = xp + (size_t)(blk + 3) * TB * BN2;
                #pragma unroll
                for (int t = 0; t < TB; t++)
                    buf[(u + 3) & 3][t] = xb[t * BN2];
            }

            float spike_out[2][TB];

            #pragma unroll
            for (int l = 0; l < 2; l++) {
                const bool  spiked = (t0p[l] < TB);
                const float maskf  = spiked ? 1.0f : 0.0f;

                // adaptation: sg one-hot at t0p -> a_at = p^(t0p+1)*a + 1/p,
                // pds = p^(TB-1-t0p)
                float pt  = ppow[l][1];
                float pds = ppow[l][TB - 1];
                #pragma unroll
                for (int k = 1; k < TB; k++)
                    if (t0p[l] == k) { pt = ppow[l][k + 1]; pds = ppow[l][TB - 1 - k]; }
                const float a_at  = __fadd_rn(__fmul_rn(pt, a[l]), inv_p[l]);
                const float new_a = __fmul_rn(a_at, pds);
                a[l] = spiked ? new_a : (ppow[l][TB] * a[l]);

                // refractory masking + membrane carry-in
                const float v_init = vmem[l] * (1.0f - maskf);
                const int   mstart = spiked ? t0p[l] : 0;
                float cur[TB];
                #pragma unroll
                for (int t = 0; t < TB; t++) {
                    const float xv = (l == 0) ? buf[u & 3][t].x : buf[u & 3][t].y;
                    cur[t] = (t < mstart) ? 0.0f : xv;
                }
                cur[0] = cur[0] + beta[l] * v_init;

                // causal decayed sums + threshold; first crossing
                int cand[TB];
                float mlast = 0.0f;
                #pragma unroll
                for (int t = 0; t < TB; t++) {
                    float m = 0.0f;
                    #pragma unroll
                    for (int s = 0; s <= t; s++)
                        m += bpow[l][t - s] * cur[s];
                    const float vth = 1.0f + bb[l] * (ppow[l][t + 1] * a[l]);
                    cand[t] = ((m - vth) > 0.0f) ? t : TB;
                    if (t == TB - 1) mlast = m;
                }
                const int m01 = min(cand[0], cand[1]);
                const int m23 = min(cand[2], cand[3]);
                const int m45 = min(cand[4], cand[5]);
                const int m67 = min(cand[6], cand[7]);
                const int t0  = min(min(m01, m23), min(m45, m67));

                #pragma unroll
                for (int t = 0; t < TB; t++)
                    spike_out[l][t] = (t == t0) ? 1.0f : 0.0f;

                t0p[l]  = t0;
                vmem[l] = mlast;
            }

            // vector stores: both lanes per t
            float2* ob = op + (size_t)blk * TB * BN2;
            #pragma unroll
            for (int t = 0; t < TB; t++) {
                float2 v;
                v.x = spike_out[0][t];
                v.y = spike_out[1][t];
                ob[t * BN2] = v;
            }
        }
    }
}

extern "C" void kernel_launch(void* const* d_in, const int* in_sizes, int n_in,
                              void* d_out, int out_size)
{
    const float* x        = (const float*)d_in[0];
    const float* beta_raw = (const float*)d_in[1];
    const float* p_raw    = (const float*)d_in[2];
    const float* b_raw    = (const float*)d_in[3];
    float* out = (float*)d_out;

    blocks_snn_kernel<<<NTHREAD / CTA, CTA>>>(x, beta_raw, p_raw, b_raw, out);
}

// round 9
// speedup vs baseline: 1.2176x; 1.2176x over previous
#include <cuda_runtime.h>

// Blocks_86096914416144 — SNN block scan, R9: 2 threads per (b,n) lane.
// Thread pair (2i,2i+1): h=0 owns t=0..3, h=1 owns t=4..7. 65536 threads ->
// 13.8 warps/SM (2x R5). Evidence R5-R8: runtime tracks warp count (serial
// fixed-lat chains unhidden at 1.7 warps/SMSP); instruction cuts never helped.
// Exactness: padded 8-term sums append +/-0 terms after the real ascending-s
// terms (sign-of-zero only feeds '>' compares); m[7] is unpadded so the vmem
// carry is bit-exact; a-update is R7's proven chain.

#define T_LEN   1024
#define TB      8
#define NBLK    (T_LEN / TB)      // 128
#define BATCH   32
#define NOUT    1024
#define BN      (BATCH * NOUT)    // 32768
#define NTHR    (2 * BN)          // 65536
#define CTA     128

__global__ __launch_bounds__(CTA)
void blocks_snn_kernel(const float* __restrict__ x,
                       const float* __restrict__ beta_raw,
                       const float* __restrict__ p_raw,
                       const float* __restrict__ b_raw,
                       float* __restrict__ out)
{
    const int tid  = blockIdx.x * CTA + threadIdx.x;   // 0..65535
    const int lane = tid >> 1;                          // (b,n) lane 0..32767
    const int h    = tid & 1;                           // timestep half
    const int n    = lane & (NOUT - 1);

    const float beta  = fminf(fmaxf(beta_raw[n], 0.001f), 0.999f);
    const float p     = fminf(fmaxf(fabsf(p_raw[n]), 0.0f), 0.999f);
    const float bb    = fminf(fmaxf(fabsf(b_raw[n]), 0.001f), 1.0f);
    const float inv_p = 1.0f / p;

    float bpow[TB];
    bpow[0] = 1.0f;
    #pragma unroll
    for (int k = 1; k < TB; k++) bpow[k] = powf(beta, (float)k);

    float ppow[TB + 1];
    ppow[0] = 1.0f;
    #pragma unroll
    for (int k = 1; k <= TB; k++) ppow[k] = powf(p, (float)k);

    // padded membrane weights: w[j][s] = bpow[(4h+j)-s] if s <= 4h+j else 0
    // (compile-time indices, runtime SEL on h -> stays in registers)
    float w[4][TB];
    #pragma unroll
    for (int j = 0; j < 4; j++) {
        #pragma unroll
        for (int s = 0; s < TB; s++) {
            const int dA = j - s;          // h = 0
            const int dB = 4 + j - s;      // h = 1
            const float vA = (dA < 0) ? 0.0f : bpow[dA];
            const float vB = (dB < 0) ? 0.0f : bpow[dB];
            w[j][s] = h ? vB : vA;
        }
    }
    // vth exponent table: ppow[(4h+j)+1]
    float myp[4];
    #pragma unroll
    for (int j = 0; j < 4; j++)
        myp[j] = h ? ppow[5 + j] : ppow[1 + j];

    const int tbase = 4 * h;

    // carry (redundant per pair where needed)
    int   t0p  = TB;
    float a    = 0.0f;
    float vmem = 0.0f;

    const float* xp = x   + lane + (size_t)tbase * BN;
    float*       op = out + lane + (size_t)tbase * BN;

    // 4-slot ring of this thread's 4 t-values, prefetch 3 blocks ahead
    float buf[4][4];
    #pragma unroll
    for (int pb = 0; pb < 3; pb++) {
        const float* xb = xp + (size_t)pb * TB * BN;
        #pragma unroll
        for (int j = 0; j < 4; j++) buf[pb][j] = xb[j * BN];
    }

    #pragma unroll 1
    for (int g = 0; g < NBLK / 4; g++) {
        #pragma unroll
        for (int u = 0; u < 4; u++) {
            const int blk = 4 * g + u;

            if (blk + 3 < NBLK) {
                const float* xb = xp + (size_t)(blk + 3) * TB * BN;
                #pragma unroll
                for (int j = 0; j < 4; j++)
                    buf[(u + 3) & 3][j] = xb[j * BN];
            }

            const bool  spiked = (t0p < TB);
            const float maskf  = spiked ? 1.0f : 0.0f;
            const int   mstart = spiked ? t0p : 0;

            // ---- adaptation update (R7 chain, redundant in both threads) ----
            float pt  = ppow[1];
            float pds = ppow[TB - 1];
            #pragma unroll
            for (int k = 1; k < TB; k++)
                if (t0p == k) { pt = ppow[k + 1]; pds = ppow[TB - 1 - k]; }
            const float a_at  = __fadd_rn(__fmul_rn(pt, a), inv_p);
            const float new_a = __fmul_rn(a_at, pds);
            a = spiked ? new_a : (ppow[TB] * a);

            // ---- own cur values (refractory mask; h==0 adds v_init term) ----
            const float v_init = vmem * (1.0f - maskf);
            float co[4];
            #pragma unroll
            for (int j = 0; j < 4; j++)
                co[j] = ((tbase + j) < mstart) ? 0.0f : buf[u & 3][j];
            if (h == 0)                                   // predicated, no branch
                co[0] = co[0] + beta * v_init;

            // ---- exchange cur with partner; canonical cs[0..7] ----
            float cx[4];
            #pragma unroll
            for (int j = 0; j < 4; j++)
                cx[j] = __shfl_xor_sync(0xFFFFFFFFu, co[j], 1);
            float cs[TB];
            #pragma unroll
            for (int j = 0; j < 4; j++) {
                cs[j]     = h ? cx[j] : co[j];
                cs[4 + j] = h ? co[j] : cx[j];
            }

            // ---- padded causal sums (ascending s, real terms first) ----
            float m[4];
            #pragma unroll
            for (int j = 0; j < 4; j++) {
                float acc = 0.0f;
                #pragma unroll
                for (int s = 0; s < TB; s++)
                    acc += w[j][s] * cs[s];
                m[j] = acc;
            }

            // ---- threshold, first-crossing index across the pair ----
            int lmin = TB;
            #pragma unroll
            for (int j = 0; j < 4; j++) {
                const float vth = 1.0f + bb * (myp[j] * a);
                const int cand = ((m[j] - vth) > 0.0f) ? (tbase + j) : TB;
                lmin = min(lmin, cand);
            }
            const int omin = __shfl_xor_sync(0xFFFFFFFFu, lmin, 1);
            const int t0   = min(lmin, omin);

            // ---- one-hot spike output (own 4 timesteps) ----
            float* ob = op + (size_t)blk * TB * BN;
            #pragma unroll
            for (int j = 0; j < 4; j++)
                ob[j * BN] = ((tbase + j) == t0) ? 1.0f : 0.0f;

            // ---- vmem = m[t=7] (h==1's m[3], bit-exact unpadded) ----
            const float mothr = __shfl_xor_sync(0xFFFFFFFFu, m[3], 1);
            vmem = h ? m[3] : mothr;
            t0p  = t0;
        }
    }
}

extern "C" void kernel_launch(void* const* d_in, const int* in_sizes, int n_in,
                              void* d_out, int out_size)
{
    const float* x        = (const float*)d_in[0];
    const float* beta_raw = (const float*)d_in[1];
    const float* p_raw    = (const float*)d_in[2];
    const float* b_raw    = (const float*)d_in[3];
    float* out = (float*)d_out;

    blocks_snn_kernel<<<NTHR / CTA, CTA>>>(x, beta_raw, p_raw, b_raw, out);
}

// round 10
// speedup vs baseline: 1.2510x; 1.0274x over previous
#include <cuda_runtime.h>

// Blocks_86096914416144 — SNN block scan, R10: 2 threads per lane, exchange-free
// split. Both threads of a pair load ALL 8 x values (adjacent threads, same
// addresses -> intra-warp broadcast, no extra DRAM traffic) and build cur[0..7]
// locally (bit-identical). Balanced t-split: h=0 owns {0,1,6,7} (18 FMA, incl.
// m[7] -> vmem), h=1 owns {2,3,4,5} (18 FMA). Cross-pair traffic per iter:
// ONE shfl round (t0 min + vmem). R9 lesson: 3 shfl rounds on the carry chain
// destroyed the occupancy win; this has 1.
// Padded sums + a-chain forms proven rel_err 0.0 in R9.

#define T_LEN   1024
#define TB      8
#define NBLK    (T_LEN / TB)      // 128
#define BATCH   32
#define NOUT    1024
#define BN      (BATCH * NOUT)    // 32768
#define NTHR    (2 * BN)          // 65536
#define CTA     128

__global__ __launch_bounds__(CTA)
void blocks_snn_kernel(const float* __restrict__ x,
                       const float* __restrict__ beta_raw,
                       const float* __restrict__ p_raw,
                       const float* __restrict__ b_raw,
                       float* __restrict__ out)
{
    const int tid  = blockIdx.x * CTA + threadIdx.x;   // 0..65535
    const int lane = tid >> 1;                          // (b,n) lane 0..32767
    const int h    = tid & 1;                           // which t-subset
    const int n    = lane & (NOUT - 1);

    const float beta  = fminf(fmaxf(beta_raw[n], 0.001f), 0.999f);
    const float p     = fminf(fmaxf(fabsf(p_raw[n]), 0.0f), 0.999f);
    const float bb    = fminf(fmaxf(fabsf(b_raw[n]), 0.001f), 1.0f);
    const float inv_p = 1.0f / p;

    float bpow[TB];
    bpow[0] = 1.0f;
    #pragma unroll
    for (int k = 1; k < TB; k++) bpow[k] = powf(beta, (float)k);

    float ppow[TB + 1];
    ppow[0] = 1.0f;
    #pragma unroll
    for (int k = 1; k <= TB; k++) ppow[k] = powf(p, (float)k);

    // owned timesteps: h=0 -> {0,1,6,7} (includes t=7 => vmem), h=1 -> {2,3,4,5}
    // padded weights w[j][s] = bpow[Tj - s] for s <= Tj else 0  (R9-proven)
    const int TA[4] = {0, 1, 6, 7};
    const int TBt[4] = {2, 3, 4, 5};
    float w[4][TB];
    float myp[4];       // ppow[Tj + 1] for vth
    int   myT[4];
    int   myOff[4];     // Tj * BN store offsets
    #pragma unroll
    for (int j = 0; j < 4; j++) {
        const int tA = TA[j], tB2 = TBt[j];
        myT[j]   = h ? tB2 : tA;
        myOff[j] = myT[j] * BN;
        myp[j]   = h ? ppow[tB2 + 1] : ppow[tA + 1];
        #pragma unroll
        for (int s = 0; s < TB; s++) {
            const float vA = (tA  - s < 0) ? 0.0f : bpow[tA  - s];
            const float vB = (tB2 - s < 0) ? 0.0f : bpow[tB2 - s];
            w[j][s] = h ? vB : vA;
        }
    }

    // carry
    int   t0p  = TB;
    float a    = 0.0f;
    float vmem = 0.0f;

    const float* xp = x   + lane;
    float*       op = out + lane;

    // 4-slot ring of all 8 t-values (pair threads load same addrs -> broadcast)
    float buf[4][TB];
    #pragma unroll
    for (int pb = 0; pb < 3; pb++) {
        const float* xb = xp + (size_t)pb * TB * BN;
        #pragma unroll
        for (int t = 0; t < TB; t++) buf[pb][t] = xb[t * BN];
    }

    #pragma unroll 1
    for (int g = 0; g < NBLK / 4; g++) {
        #pragma unroll
        for (int u = 0; u < 4; u++) {
            const int blk = 4 * g + u;

            if (blk + 3 < NBLK) {
                const float* xb = xp + (size_t)(blk + 3) * TB * BN;
                #pragma unroll
                for (int t = 0; t < TB; t++)
                    buf[(u + 3) & 3][t] = xb[t * BN];
            }

            const bool  spiked = (t0p < TB);
            const float maskf  = spiked ? 1.0f : 0.0f;
            const int   mstart = spiked ? t0p : 0;

            // ---- adaptation update (redundant per thread; R7/R9 exact chain) ----
            float pt  = ppow[1];
            float pds = ppow[TB - 1];
            #pragma unroll
            for (int k = 1; k < TB; k++)
                if (t0p == k) { pt = ppow[k + 1]; pds = ppow[TB - 1 - k]; }
            const float a_at  = __fadd_rn(__fmul_rn(pt, a), inv_p);
            const float new_a = __fmul_rn(a_at, pds);
            a = spiked ? new_a : (ppow[TB] * a);

            // ---- cur[0..7], built identically in both threads ----
            const float v_init = vmem * (1.0f - maskf);
            float cur[TB];
            #pragma unroll
            for (int t = 0; t < TB; t++)
                cur[t] = (t < mstart) ? 0.0f : buf[u & 3][t];
            cur[0] = cur[0] + beta * v_init;

            // ---- own 4 padded causal sums (ascending s, R9-proven exact) ----
            float m[4];
            #pragma unroll
            for (int j = 0; j < 4; j++) {
                float acc = 0.0f;
                #pragma unroll
                for (int s = 0; s < TB; s++)
                    acc += w[j][s] * cur[s];
                m[j] = acc;
            }

            // ---- threshold + local first-crossing ----
            int lmin = TB;
            #pragma unroll
            for (int j = 0; j < 4; j++) {
                const float vth = 1.0f + bb * (myp[j] * a);
                const int cand = ((m[j] - vth) > 0.0f) ? myT[j] : TB;
                lmin = min(lmin, cand);
            }

            // ---- single exchange round: t0 min + vmem (m[t=7] from h=0) ----
            const int   omin  = __shfl_xor_sync(0xFFFFFFFFu, lmin, 1);
            const float mpart = __shfl_xor_sync(0xFFFFFFFFu, m[3], 1);
            const int t0 = min(lmin, omin);
            vmem = h ? mpart : m[3];        // h=0's m[3] is the exact m[t=7]

            // ---- one-hot spike output (own 4 timesteps) ----
            float* ob = op + (size_t)blk * TB * BN;
            #pragma unroll
            for (int j = 0; j < 4; j++)
                ob[myOff[j]] = (myT[j] == t0) ? 1.0f : 0.0f;

            t0p = t0;
        }
    }
}

extern "C" void kernel_launch(void* const* d_in, const int* in_sizes, int n_in,
                              void* d_out, int out_size)
{
    const float* x        = (const float*)d_in[0];
    const float* beta_raw = (const float*)d_in[1];
    const float* p_raw    = (const float*)d_in[2];
    const float* b_raw    = (const float*)d_in[3];
    float* out = (float*)d_out;

    blocks_snn_kernel<<<NTHR / CTA, CTA>>>(x, beta_raw, p_raw, b_raw, out);
}